// round 15
// baseline (speedup 1.0000x reference)
#include <cuda_runtime.h>
#include <cstdint>

// ---------------------------------------------------------------------------
// TransferSH R10: R9 (warp-cooperative coalesced gather) with the smem layout
// bug fixed.
//
// R9 bug: base_sh window stored at row floats 46..49 overlapped the 48-float
// higher_sh window (floats 0..47) -> clobbered floats 46,47 for id&3==3 rows
// (rel_err 0.149). Fix: base window lives at floats 48..51 (ROW_STRIDE=52).
//
// Design (unchanged from R9):
//   - per-warp: 32 row-ids staged in smem, broadcast-read by cooperative lanes
//   - Phase A: chunks 0..7 of each row, 4 rows/instruction (coalesced 128B)
//   - Phase B: chunks 8..11, 8 rows/instruction (coalesced 64B)
//   - Phase C: base_sh float2 window, 16 rows/instruction
//   - raw STS.128/STS.64 stores; rotation applied by consumer as one dynamic
//     base offset (id&3 / id&1), then compile-time LDS offsets
// Wavefront ledger: ~170/warp-pass vs ~500 for per-lane gather (R4/R6 wall).
//
// Output layout (float32): [ clipped colors (N*3) , mean_abs scalar (1) ]
// ---------------------------------------------------------------------------

__device__ float g_affine[12];   // row-major 3x4, eye added

#define SH_C0 0.28209479177387814f
#define SH_C1 0.4886025119029199f
#define SH_C2_0 1.0925484305920792f
#define SH_C2_1 (-1.0925484305920792f)
#define SH_C2_2 0.31539156525252005f
#define SH_C2_3 (-1.0925484305920792f)
#define SH_C2_4 0.5462742152960396f
#define SH_C3_0 (-0.5900435899266435f)
#define SH_C3_1 2.890611442640554f
#define SH_C3_2 (-0.4570457994644658f)
#define SH_C3_3 0.3731763325901154f
#define SH_C3_4 (-0.4570457994644658f)
#define SH_C3_5 1.445305721320277f
#define SH_C3_6 (-0.5900435899266435f)

// ---------------------------------------------------------------------------
// Kernel A: 1x16 -> 32 (LN, relu) -> 12 MLP, affine build, mean|.|
// ---------------------------------------------------------------------------
__global__ void affine_kernel(const float* __restrict__ glo,
                              const float* __restrict__ w1,
                              const float* __restrict__ b1,
                              const float* __restrict__ ln_w,
                              const float* __restrict__ ln_b,
                              const float* __restrict__ w2,
                              const float* __restrict__ b2,
                              float* __restrict__ out_scalar)
{
    if (threadIdx.x != 0 || blockIdx.x != 0) return;

    float g[16];
#pragma unroll
    for (int k = 0; k < 16; k++) g[k] = glo[k];

    float h[32];
    float mu = 0.f;
#pragma unroll
    for (int j = 0; j < 32; j++) {
        float acc = b1[j];
#pragma unroll
        for (int k = 0; k < 16; k++) acc += g[k] * w1[k * 32 + j];
        h[j] = acc;
        mu += acc;
    }
    mu *= (1.f / 32.f);
    float var = 0.f;
#pragma unroll
    for (int j = 0; j < 32; j++) {
        float d = h[j] - mu;
        var += d * d;
    }
    var *= (1.f / 32.f);
    float inv = rsqrtf(var + 1e-5f);
#pragma unroll
    for (int j = 0; j < 32; j++) {
        float v = (h[j] - mu) * inv * ln_w[j] + ln_b[j];
        h[j] = v > 0.f ? v : 0.f;
    }

    float s = 0.f;
#pragma unroll
    for (int c = 0; c < 12; c++) {
        float o = b2[c];
#pragma unroll
        for (int j = 0; j < 32; j++) o += h[j] * w2[j * 12 + c];
        o *= 1e-12f;
        s += fabsf(o);
        g_affine[c] = o;
    }
    g_affine[0]  += 1.f;
    g_affine[5]  += 1.f;
    g_affine[10] += 1.f;

    *out_scalar = s * (1.f / 12.f);
}

// ---------------------------------------------------------------------------
// Kernel B
// ---------------------------------------------------------------------------
#define TSH_THREADS 128
#define ROW_STRIDE  52   // floats/row: 48 higher window @0..47, base @48..51

__global__ void __launch_bounds__(TSH_THREADS, 8)
transfer_sh_kernel(const float* __restrict__ positions,   // (N,3)
                   const int*   __restrict__ indexes,     // (N,)
                   const float* __restrict__ cam_pos,     // (3,)
                   const float* __restrict__ base_sh,     // (NP,3,1)
                   const float* __restrict__ higher_sh,   // (NP,3,15)
                   float*       __restrict__ out,         // (N,3)
                   int n)
{
    __shared__ int   s_id[TSH_THREADS];
    __shared__ float s_row[TSH_THREADS * ROW_STRIDE];

    const int t     = threadIdx.x;
    const int lane  = t & 31;
    const int warp  = t >> 5;
    const int wbase = warp * 32;
    const int i     = blockIdx.x * TSH_THREADS + t;
    const int ic    = i < n ? i : (n - 1);

    float* wrow = s_row + wbase * ROW_STRIDE;

    // ---- stage this warp's 32 row-ids (warp-private region) ----
    const int id = __ldg(indexes + ic);
    s_id[t] = id;
    __syncwarp();

    const float4* hi4 = (const float4*)higher_sh;
    const float2* bs2 = (const float2*)base_sh;

    // ======== Phase A: chunks 0..7, 4 rows per instruction ========
    {
        const int rsub = lane >> 3;        // 0..3
        const int c    = lane & 7;         // chunk 0..7
        float4 v[8];
#pragma unroll
        for (int g = 0; g < 8; g++) {
            int rid = s_id[wbase + g * 4 + rsub];
            unsigned fs = (unsigned)rid * 45u;
            v[g] = __ldg(hi4 + (fs >> 2) + c);
        }
#pragma unroll
        for (int g = 0; g < 8; g++) {
            int r = g * 4 + rsub;
            *(float4*)(wrow + r * ROW_STRIDE + c * 4) = v[g];
        }
    }

    // ======== Phase B: chunks 8..11, 8 rows per instruction ========
    {
        const int rsub = lane >> 2;        // 0..7
        const int c    = 8 + (lane & 3);   // chunk 8..11
        float4 v[4];
#pragma unroll
        for (int g = 0; g < 4; g++) {
            int rid = s_id[wbase + g * 8 + rsub];
            unsigned fs = (unsigned)rid * 45u;
            v[g] = __ldg(hi4 + (fs >> 2) + c);
        }
#pragma unroll
        for (int g = 0; g < 4; g++) {
            int r = g * 8 + rsub;
            *(float4*)(wrow + r * ROW_STRIDE + c * 4) = v[g];
        }
    }

    // ======== Phase C: base_sh, 16 rows x 2 float2-chunks per instruction ===
    // base row = floats [3*rid, 3*rid+3); float2 window from floor(3*rid/2),
    // two chunks raw-stored at row floats 48..51; consumer offset (id&1).
    {
        const int rsub = lane >> 1;        // 0..15
        const int m    = lane & 1;         // chunk 0/1
        float2 v[2];
#pragma unroll
        for (int g = 0; g < 2; g++) {
            int rid = s_id[wbase + g * 16 + rsub];
            unsigned fs3 = (unsigned)rid * 3u;
            v[g] = __ldg(bs2 + (fs3 >> 1) + m);
        }
#pragma unroll
        for (int g = 0; g < 2; g++) {
            int r = g * 16 + rsub;
            *(float2*)(wrow + r * ROW_STRIDE + 48 + 2 * m) = v[g];
        }
    }

    __syncwarp();

    // ======== per-thread consume ========
    float dx = __ldg(positions + 3 * ic + 0) - __ldg(cam_pos + 0);
    float dy = __ldg(positions + 3 * ic + 1) - __ldg(cam_pos + 1);
    float dz = __ldg(positions + 3 * ic + 2) - __ldg(cam_pos + 2);
    float rinv = rsqrtf(dx * dx + dy * dy + dz * dz);
    float x = dx * rinv, y = dy * rinv, z = dz * rinv;

    float xx = x * x, yy = y * y, zz = z * z;
    float xy = x * y, yz = y * z, xz = x * z;

    float basis[15];
    basis[0]  = -SH_C1 * y;
    basis[1]  =  SH_C1 * z;
    basis[2]  = -SH_C1 * x;
    basis[3]  = SH_C2_0 * xy;
    basis[4]  = SH_C2_1 * yz;
    basis[5]  = SH_C2_2 * (2.f * zz - xx - yy);
    basis[6]  = SH_C2_3 * xz;
    basis[7]  = SH_C2_4 * (xx - yy);
    basis[8]  = SH_C3_0 * y * (3.f * xx - yy);
    basis[9]  = SH_C3_1 * xy * z;
    basis[10] = SH_C3_2 * y * (4.f * zz - xx - yy);
    basis[11] = SH_C3_3 * z * (2.f * zz - 3.f * xx - 3.f * yy);
    basis[12] = SH_C3_4 * x * (4.f * zz - xx - yy);
    basis[13] = SH_C3_5 * z * (xx - yy);
    basis[14] = SH_C3_6 * x * (xx - yy);

    const float* row  = wrow + lane * ROW_STRIDE;
    const float* hrow = row + (id & 3);          // 45*id mod 4 == id mod 4
    const float* brow = row + 48 + (id & 1);     // 3*id  mod 2 == id mod 2

    float col[3];
#pragma unroll
    for (int c = 0; c < 3; c++) {
        float acc = brow[c] * SH_C0 + 0.5f;
#pragma unroll
        for (int k = 0; k < 15; k++)
            acc += hrow[c * 15 + k] * basis[k];
        col[c] = acc;
    }

    if (i < n) {
#pragma unroll
        for (int r = 0; r < 3; r++) {
            float o = g_affine[r * 4 + 0] * col[0]
                    + g_affine[r * 4 + 1] * col[1]
                    + g_affine[r * 4 + 2] * col[2]
                    + g_affine[r * 4 + 3];
            o = fminf(fmaxf(o, 0.f), 1.f);
            out[3 * i + r] = o;
        }
    }
}

// ---------------------------------------------------------------------------
// kernel_launch
// input order: positions, indexes, cam_pos, glo_feature, base_sh, higher_sh,
//              w1, b1, ln_w, ln_b, w2, b2
// ---------------------------------------------------------------------------
extern "C" void kernel_launch(void* const* d_in, const int* in_sizes, int n_in,
                              void* d_out, int out_size)
{
    const float* positions = (const float*)d_in[0];
    const int*   indexes   = (const int*)  d_in[1];
    const float* cam_pos   = (const float*)d_in[2];
    const float* glo       = (const float*)d_in[3];
    const float* base_sh   = (const float*)d_in[4];
    const float* higher_sh = (const float*)d_in[5];
    const float* w1        = (const float*)d_in[6];
    const float* b1        = (const float*)d_in[7];
    const float* ln_w      = (const float*)d_in[8];
    const float* ln_b      = (const float*)d_in[9];
    const float* w2        = (const float*)d_in[10];
    const float* b2        = (const float*)d_in[11];

    float* out = (float*)d_out;
    int n = in_sizes[0] / 3;   // positions is (N,3)

    float* out_scalar = out + (out_size - 1);

    affine_kernel<<<1, 32>>>(glo, w1, b1, ln_w, ln_b, w2, b2, out_scalar);

    int blocks = (n + TSH_THREADS - 1) / TSH_THREADS;
    transfer_sh_kernel<<<blocks, TSH_THREADS>>>(positions, indexes, cam_pos,
                                                base_sh, higher_sh, out, n);
}

// round 17
// speedup vs baseline: 1.2538x; 1.2538x over previous
#include <cuda_runtime.h>
#include <cstdint>

// ---------------------------------------------------------------------------
// TransferSH R11: unconditional per-lane gather + branchless SEL-rotation.
//
// Evidence: R4 124us (4 divergent exposures, 48 regs); R5 173us (1 exposure,
// 72 regs, occ 32%); cooperative smem variants 214us (L1 work unchanged,
// concurrency halved). The gather ADDRESSES never depended on the rotation
// offset -- only the consume did. So: 12 unconditional LDG.128 (1 exposure),
// then branchless consume r[k] = f[k+off] via two predicated selects
// (s2 = off&2, s1 = off&1), fused into the dot product in ascending k so
// f[] liveness decays and the whole thing fits ~64 regs (launch_bounds 256,4).
// SELs ride the near-empty ALU pipe; no divergence, no smem, no sync.
//
// affine mini-kernel parallelized across 32 lanes (was 1 serial thread).
//
// Output layout (float32): [ clipped colors (N*3) , mean_abs scalar (1) ]
// ---------------------------------------------------------------------------

__device__ float g_affine[12];   // row-major 3x4, eye added

#define SH_C0 0.28209479177387814f
#define SH_C1 0.4886025119029199f
#define SH_C2_0 1.0925484305920792f
#define SH_C2_1 (-1.0925484305920792f)
#define SH_C2_2 0.31539156525252005f
#define SH_C2_3 (-1.0925484305920792f)
#define SH_C2_4 0.5462742152960396f
#define SH_C3_0 (-0.5900435899266435f)
#define SH_C3_1 2.890611442640554f
#define SH_C3_2 (-0.4570457994644658f)
#define SH_C3_3 0.3731763325901154f
#define SH_C3_4 (-0.4570457994644658f)
#define SH_C3_5 1.445305721320277f
#define SH_C3_6 (-0.5900435899266435f)

// ---------------------------------------------------------------------------
// Kernel A: 1x16 -> 32 (LN, relu) -> 12 MLP, lane-parallel (32 threads).
// lane j owns hidden unit j; outputs computed by lanes 0..11.
// ---------------------------------------------------------------------------
__global__ void affine_kernel(const float* __restrict__ glo,
                              const float* __restrict__ w1,
                              const float* __restrict__ b1,
                              const float* __restrict__ ln_w,
                              const float* __restrict__ ln_b,
                              const float* __restrict__ w2,
                              const float* __restrict__ b2,
                              float* __restrict__ out_scalar)
{
    __shared__ float s_h[32];
    const int j = threadIdx.x;   // 0..31

    // h_j = b1[j] + sum_k glo[k] * w1[k*32 + j]   (w1 loads coalesced over j)
    float acc = __ldg(b1 + j);
#pragma unroll
    for (int k = 0; k < 16; k++)
        acc += __ldg(glo + k) * __ldg(w1 + k * 32 + j);

    // mean
    float mu = acc;
#pragma unroll
    for (int m = 16; m > 0; m >>= 1)
        mu += __shfl_xor_sync(0xffffffffu, mu, m);
    mu *= (1.f / 32.f);

    // variance
    float d = acc - mu;
    float var = d * d;
#pragma unroll
    for (int m = 16; m > 0; m >>= 1)
        var += __shfl_xor_sync(0xffffffffu, var, m);
    var *= (1.f / 32.f);

    float inv = rsqrtf(var + 1e-5f);
    float h = (acc - mu) * inv * __ldg(ln_w + j) + __ldg(ln_b + j);
    h = h > 0.f ? h : 0.f;
    s_h[j] = h;
    __syncwarp();

    // lanes 0..11: o_c = (b2[c] + sum_j h_j * w2[j*12+c]) * 1e-12
    float o = 0.f;
    float a = 0.f;
    if (j < 12) {
        o = __ldg(b2 + j);
#pragma unroll
        for (int k = 0; k < 32; k++)
            o += s_h[k] * __ldg(w2 + k * 12 + j);
        o *= 1e-12f;
        a = fabsf(o);
        float e = (j == 0 || j == 5 || j == 10) ? 1.f : 0.f;
        g_affine[j] = o + e;
    }
    // mean |o| over the 12 lanes
#pragma unroll
    for (int m = 16; m > 0; m >>= 1)
        a += __shfl_xor_sync(0xffffffffu, a, m);
    if (j == 0) *out_scalar = a * (1.f / 12.f);
}

// ---------------------------------------------------------------------------
// Kernel B: per-point SH evaluation, branchless rotated gather consume.
// ---------------------------------------------------------------------------
__global__ void __launch_bounds__(256, 4)
transfer_sh_kernel(const float* __restrict__ positions,   // (N,3)
                   const int*   __restrict__ indexes,     // (N,)
                   const float* __restrict__ cam_pos,     // (3,)
                   const float* __restrict__ base_sh,     // (NP,3,1)
                   const float* __restrict__ higher_sh,   // (NP,3,15)
                   float*       __restrict__ out,         // (N,3)
                   int n)
{
    int i = blockIdx.x * blockDim.x + threadIdx.x;
    if (i >= n) return;

    // ---- index, then all gathers issued unconditionally (1 exposure) ----
    int id = __ldg(indexes + i);
    unsigned fs = (unsigned)id * 45u;                 // < 2^31
    const float4* q = (const float4*)higher_sh + (fs >> 2);
    // window bytes [ (fs>>2)*16, +192 ); max end = exactly 90M floats. safe.

    float f[48];
#pragma unroll
    for (int j = 0; j < 12; j++) {
        float4 t = __ldg(q + j);
        f[4 * j + 0] = t.x;
        f[4 * j + 1] = t.y;
        f[4 * j + 2] = t.z;
        f[4 * j + 3] = t.w;
    }

    const float* brow = base_sh + (unsigned)id * 3u;
    float b0  = __ldg(brow + 0);
    float b1v = __ldg(brow + 1);
    float b2v = __ldg(brow + 2);

    // ---- direction + SH basis (overlaps gather latency) ----
    float dx = __ldg(positions + 3 * i + 0) - __ldg(cam_pos + 0);
    float dy = __ldg(positions + 3 * i + 1) - __ldg(cam_pos + 1);
    float dz = __ldg(positions + 3 * i + 2) - __ldg(cam_pos + 2);
    float rinv = rsqrtf(dx * dx + dy * dy + dz * dz);
    float x = dx * rinv, y = dy * rinv, z = dz * rinv;

    float xx = x * x, yy = y * y, zz = z * z;
    float xy = x * y, yz = y * z, xz = x * z;

    float basis[15];
    basis[0]  = -SH_C1 * y;
    basis[1]  =  SH_C1 * z;
    basis[2]  = -SH_C1 * x;
    basis[3]  = SH_C2_0 * xy;
    basis[4]  = SH_C2_1 * yz;
    basis[5]  = SH_C2_2 * (2.f * zz - xx - yy);
    basis[6]  = SH_C2_3 * xz;
    basis[7]  = SH_C2_4 * (xx - yy);
    basis[8]  = SH_C3_0 * y * (3.f * xx - yy);
    basis[9]  = SH_C3_1 * xy * z;
    basis[10] = SH_C3_2 * y * (4.f * zz - xx - yy);
    basis[11] = SH_C3_3 * z * (2.f * zz - 3.f * xx - 3.f * yy);
    basis[12] = SH_C3_4 * x * (4.f * zz - xx - yy);
    basis[13] = SH_C3_5 * z * (xx - yy);
    basis[14] = SH_C3_6 * x * (xx - yy);

    float col[3];
    col[0] = b0  * SH_C0 + 0.5f;
    col[1] = b1v * SH_C0 + 0.5f;
    col[2] = b2v * SH_C0 + 0.5f;

    // ---- branchless rotation fused with dot product ----
    // r_k = f[k + off], off = fs & 3. Ascending k => f[] liveness decays.
    const bool s1 = (fs & 1u) != 0u;
    const bool s2 = (fs & 2u) != 0u;
#pragma unroll
    for (int k = 0; k < 45; k++) {
        float a0 = s2 ? f[k + 2] : f[k];
        float a1 = s2 ? f[k + 3] : f[k + 1];   // == a0 of iteration k+1 (CSE)
        float rk = s1 ? a1 : a0;
        col[k / 15] += rk * basis[k % 15];
    }

    // ---- affine + clamp + store ----
#pragma unroll
    for (int r = 0; r < 3; r++) {
        float o = g_affine[r * 4 + 0] * col[0]
                + g_affine[r * 4 + 1] * col[1]
                + g_affine[r * 4 + 2] * col[2]
                + g_affine[r * 4 + 3];
        o = fminf(fmaxf(o, 0.f), 1.f);
        out[3 * i + r] = o;
    }
}

// ---------------------------------------------------------------------------
// kernel_launch
// input order: positions, indexes, cam_pos, glo_feature, base_sh, higher_sh,
//              w1, b1, ln_w, ln_b, w2, b2
// ---------------------------------------------------------------------------
extern "C" void kernel_launch(void* const* d_in, const int* in_sizes, int n_in,
                              void* d_out, int out_size)
{
    const float* positions = (const float*)d_in[0];
    const int*   indexes   = (const int*)  d_in[1];
    const float* cam_pos   = (const float*)d_in[2];
    const float* glo       = (const float*)d_in[3];
    const float* base_sh   = (const float*)d_in[4];
    const float* higher_sh = (const float*)d_in[5];
    const float* w1        = (const float*)d_in[6];
    const float* b1        = (const float*)d_in[7];
    const float* ln_w      = (const float*)d_in[8];
    const float* ln_b      = (const float*)d_in[9];
    const float* w2        = (const float*)d_in[10];
    const float* b2        = (const float*)d_in[11];

    float* out = (float*)d_out;
    int n = in_sizes[0] / 3;   // positions is (N,3)

    float* out_scalar = out + (out_size - 1);

    affine_kernel<<<1, 32>>>(glo, w1, b1, ln_w, ln_b, w2, b2, out_scalar);

    int threads = 256;
    int blocks = (n + threads - 1) / threads;
    transfer_sh_kernel<<<blocks, threads>>>(positions, indexes, cam_pos,
                                            base_sh, higher_sh, out, n);
}